// round 15
// baseline (speedup 1.0000x reference)
#include <cuda_runtime.h>
#include <cuda_fp16.h>
#include <math.h>

// ---------------- problem constants ----------------
#define Tn 4
#define Bn 2
#define Cch 128
#define Psp 8192              // 8*32*32
#define Nimg 8                // Tn*Bn
#define TOT 8388608           // Nimg*Cch*Psp
#define NW 8
#define Swin 1024
#define HDIM 16
#define TOPK 4
#define THETA 0.7f
#define EPS_BN 1e-5
// A: fragment-native layout, 16384 B/stage (no padding)
// B: [2 split][256 p][40 halves] rows of 80 B, 20480 B/stage
#define B_OFF 16384
#define STAGE_BYTES 36864
#define SMEM_TOTAL 110592     // 3 stages

// ---------------- device scratch ----------------
__device__ float g_qpre[TOT];
__device__ float g_kpre[TOT];
__device__ unsigned char g_qspk[TOT];   // u8 spikes, windowed [t][b][w][c][s]
__device__ unsigned char g_kspk[TOT];
__device__ unsigned char g_vspk[TOT];
__device__ float g_y[TOT];
__device__ float g_mean[4 * 128];
__device__ float g_rstd[4 * 128];
__device__ float g_regsum[2 * Bn * NW * 128];   // BN'd window sums (q,k)
__device__ int   g_topidx[Bn * NW * TOPK];
__device__ double g_part[4 * 2048 * 2];
__device__ double g_pxs[2048 * 64];     // x channel partials from prep_all
__device__ double g_pxss[2048 * 64];

// weight images, fragment-native: per stage 1024 uint4 (16384 B)
__device__ uint4 g_wA4[112 * 1024];
__device__ uint4 g_kwimg[4 * 1024];
__device__ uint4 g_pwimg[4 * 1024];
// x transposed + fp16-split: [n*8192 + p][64 u32]
__device__ unsigned int g_xh32[Nimg * Psp * 64];
__device__ unsigned int g_xl32[Nimg * Psp * 64];
// spike output of attn in fp16 [n][p][c]
__device__ unsigned int g_s2h[TOT / 2];

// ---------------- helpers ----------------
__device__ __forceinline__ unsigned int smem_u32(const void* p) {
    unsigned int a;
    asm("{ .reg .u64 t; cvta.to.shared.u64 t, %1; cvt.u32.u64 %0, t; }" : "=r"(a) : "l"(p));
    return a;
}
__device__ __forceinline__ void cpa16(unsigned int dst, const void* src, int srcbytes) {
    asm volatile("cp.async.cg.shared.global [%0], [%1], 16, %2;"
                 :: "r"(dst), "l"(src), "r"(srcbytes) : "memory");
}
#define CPA_COMMIT() asm volatile("cp.async.commit_group;" ::: "memory")
#define CPA_WAIT1()  asm volatile("cp.async.wait_group 1;" ::: "memory")
#define CPA_WAIT0()  asm volatile("cp.async.wait_group 0;" ::: "memory")

__device__ __forceinline__ void ldsm_x4(unsigned int* r, unsigned int addr) {
    asm volatile("ldmatrix.sync.aligned.m8n8.x4.shared.b16 {%0,%1,%2,%3}, [%4];"
                 : "=r"(r[0]), "=r"(r[1]), "=r"(r[2]), "=r"(r[3]) : "r"(addr));
}
__device__ __forceinline__ void mma16816(float* c, const unsigned int* a,
                                         unsigned int b0, unsigned int b1) {
    asm volatile("mma.sync.aligned.m16n8k16.row.col.f32.f16.f16.f32 "
                 "{%0,%1,%2,%3}, {%4,%5,%6,%7}, {%8,%9}, {%0,%1,%2,%3};"
                 : "+f"(c[0]), "+f"(c[1]), "+f"(c[2]), "+f"(c[3])
                 : "r"(a[0]), "r"(a[1]), "r"(a[2]), "r"(a[3]), "r"(b0), "r"(b1));
}
__device__ __forceinline__ void split2h(float x, unsigned short& h, unsigned short& l) {
    __half hh = __float2half_rn(x);
    float fh = __half2float(hh);
    __half hl = __float2half_rn(x - fh);
    h = __half_as_ushort(hh);
    l = __half_as_ushort(hl);
}

// A image half-index within a stage block (8192 halves):
// [split(2)][koct(4)][ogrp(16)][orow(8)][khalf(8)]
__device__ __forceinline__ int a_img_idx(int split, int o, int kh) {
    return split * 4096 + (kh >> 3) * 1024 + (o >> 3) * 64 + (o & 7) * 8 + (kh & 7);
}

// ---------------- combined prep: xsplit (2048 CTAs, + x stats) + wimgs ----------------
__global__ __launch_bounds__(256) void prep_all_kernel(const float* __restrict__ x,
                                                       const float* __restrict__ qw,
                                                       const float* __restrict__ kw,
                                                       const float* __restrict__ pw) {
    __shared__ float sm[64 * 65];
    int bx = blockIdx.x;
    int tid = threadIdx.x;

    if (bx < 2048) {
        int n  = bx >> 8;
        int cg = (bx >> 7) & 1;
        int pg = bx & 127;
        int c0 = cg * 64, p0 = pg * 64;
        #pragma unroll
        for (int i = 0; i < 16; i++) {
            int idx = tid + i * 256;
            int cc = idx >> 6, pp = idx & 63;
            sm[cc * 65 + pp] = x[((size_t)(n * 128 + c0 + cc)) * Psp + p0 + pp];
        }
        __syncthreads();
        #pragma unroll
        for (int i = 0; i < 8; i++) {
            int idx = tid + i * 256;
            int pp = idx >> 5, k = idx & 31;
            float v0 = sm[(2 * k) * 65 + pp];
            float v1 = sm[(2 * k + 1) * 65 + pp];
            unsigned short h0, l0, h1, l1;
            split2h(v0, h0, l0);
            split2h(v1, h1, l1);
            size_t dst = ((size_t)(n * Psp + p0 + pp)) * 64 + cg * 32 + k;
            g_xh32[dst] = (unsigned int)h0 | ((unsigned int)h1 << 16);
            g_xl32[dst] = (unsigned int)l0 | ((unsigned int)l1 << 16);
        }
        // x channel partials (deterministic)
        if (tid < 64) {
            double s = 0.0, ss = 0.0;
            for (int pp = 0; pp < 64; pp++) {
                float vv = sm[tid * 65 + pp];
                s += vv;
                ss += (double)vv * vv;
            }
            g_pxs[(size_t)bx * 64 + tid]  = s;
            g_pxss[(size_t)bx * 64 + tid] = ss;
        }
        return;
    }
    if (bx < 2112) {
        int t2 = (bx - 2048) * 256 + tid;      // 16384
        int o = t2 >> 7;
        int ic = t2 & 127;
        int kc = ic >> 5;
        int kh = ic & 31;
        unsigned short* img = (unsigned short*)g_wA4;
        float kd = 0.f;
        #pragma unroll
        for (int t = 0; t < 27; t++) {
            float w = qw[o * 3456 + ic * 27 + t];
            if ((t / 9) != 1) kd += w;
            unsigned short h, l;
            split2h(w, h, l);
            int s = t * 4 + kc;
            img[s * 8192 + a_img_idx(0, o, kh)] = h;
            img[s * 8192 + a_img_idx(1, o, kh)] = l;
        }
        {
            unsigned short h, l;
            split2h(-THETA * kd, h, l);
            int s = 27 * 4 + kc;
            img[s * 8192 + a_img_idx(0, o, kh)] = h;
            img[s * 8192 + a_img_idx(1, o, kh)] = l;
        }
        return;
    }
    {
        int t2 = (bx - 2112) * 256 + tid;      // 16384
        int o = t2 >> 7;
        int ic = t2 & 127;
        int s = ic >> 5;
        int kh = ic & 31;
        unsigned short* ki = (unsigned short*)g_kwimg;
        unsigned short* pi = (unsigned short*)g_pwimg;
        unsigned short h, l;
        split2h(kw[o * 128 + ic], h, l);
        ki[s * 8192 + a_img_idx(0, o, kh)] = h;
        ki[s * 8192 + a_img_idx(1, o, kh)] = l;
        split2h(pw[o * 128 + ic], h, l);
        pi[s * 8192 + a_img_idx(0, o, kh)] = h;
        pi[s * 8192 + a_img_idx(1, o, kh)] = l;
    }
}

// ---------------- tensor-core GEMM/conv (fp16 2-split), 3-deep pipeline ----------------
__global__ __launch_bounds__(256, 2) void mma_gemm_kernel(
    const uint4* __restrict__ wimgA, int tapbaseA, int nsA, float* __restrict__ outA,
    const uint4* __restrict__ wimgB, int tapbaseB, int nsB, float* __restrict__ outB,
    int use_bl,
    const unsigned int* __restrict__ xh, const unsigned int* __restrict__ xl)
{
    extern __shared__ __align__(16) unsigned char smem[];
    const unsigned int sbase = smem_u32(smem);
    const int tid = threadIdx.x;
    const int lane = tid & 31, wid = tid >> 5;
    const int g = lane >> 2, tq = lane & 3;

    const int grp = blockIdx.x >> 9;
    const int bid = blockIdx.x & 511;
    const uint4* wimg = grp ? wimgB : wimgA;
    const int tapbase = grp ? tapbaseB : tapbaseA;
    const int nstage  = grp ? nsB : nsA;
    float* out        = grp ? outB : outA;

    const int n  = bid >> 6;
    const int p0 = (bid & 63) << 7;
    const int o0 = (wid >> 1) * 32;
    const int pb = (wid & 1) * 64;

    const int sp = tid & 1, prow = tid >> 1;
    const int pg = p0 + prow;
    const int pd = pg >> 10, ph = (pg >> 5) & 31, pw_ = pg & 31;
    const unsigned int* xsrc = sp ? xl : xh;

    const int l7 = lane & 7, lm = lane >> 3;
    const unsigned int aCom = (unsigned)(((o0 >> 3) + (lm & 1)) * 128
                                         + (lm >> 1) * 2048 + l7 * 16);
    const unsigned int bCom = (unsigned)B_OFF + (unsigned)((pb + ((lm >> 1) << 3) + l7) * 80
                                         + ((lm & 1) << 4));

    float acc[2][8][4];
    #pragma unroll
    for (int mt = 0; mt < 2; mt++)
        #pragma unroll
        for (int nt = 0; nt < 8; nt++)
            #pragma unroll
            for (int q = 0; q < 4; q++) acc[mt][nt][q] = 0.f;

    auto stage_load = [&](int s) {
        unsigned int buf = sbase + (unsigned)(s % 3) * (unsigned)STAGE_BYTES;
        int tap = tapbase + (s >> 2);
        int dd, dh, dw;
        if (tap < 27) { dd = tap / 9 - 1; dh = (tap / 3) % 3 - 1; dw = tap % 3 - 1; }
        else          { dd = 0; dh = 0; dw = 0; }
        const uint4* asrc = wimg + (size_t)s * 1024;
        #pragma unroll
        for (int q = 0; q < 4; q++)
            cpa16(buf + (unsigned)(tid + q * 256) * 16u, asrc + tid + q * 256, 16);
        if (use_bl || sp == 0) {
            int d2 = pd + dd, h2 = ph + dh, w2 = pw_ + dw;
            bool val = ((unsigned)d2 < 8) & ((unsigned)h2 < 32) & ((unsigned)w2 < 32);
            int psrc = val ? (d2 * 1024 + h2 * 32 + w2) : 0;
            int kc = s & 3;
            const uint4* bsrc = (const uint4*)(xsrc + ((size_t)(n * Psp + psrc)) * 64 + kc * 16);
            unsigned int bdst = buf + (unsigned)B_OFF + (unsigned)(sp * 128 + prow) * 80u;
            int sb = val ? 16 : 0;
            #pragma unroll
            for (int q = 0; q < 4; q++)
                cpa16(bdst + q * 16u, bsrc + q, sb);
        }
        CPA_COMMIT();
    };

    stage_load(0);
    if (nstage > 1) stage_load(1);
    for (int s = 0; s < nstage; s++) {
        if (s + 1 < nstage) { CPA_WAIT1(); }
        else                { CPA_WAIT0(); }
        __syncthreads();
        if (s + 2 < nstage) stage_load(s + 2);
        unsigned int buf = sbase + (unsigned)(s % 3) * (unsigned)STAGE_BYTES;
        #pragma unroll
        for (int ks = 0; ks < 2; ks++) {
            unsigned int a[2][2][4];
            #pragma unroll
            for (int sp2 = 0; sp2 < 2; sp2++)
                #pragma unroll
                for (int mt = 0; mt < 2; mt++)
                    ldsm_x4(a[sp2][mt], buf + aCom + (unsigned)sp2 * 8192u
                                        + (unsigned)ks * 4096u + (unsigned)mt * 256u);
            #pragma unroll
            for (int ntp = 0; ntp < 4; ntp++) {
                unsigned int bd = buf + bCom + (unsigned)ntp * 1280u + (unsigned)ks * 32u;
                unsigned int bh[4], bl[4];
                ldsm_x4(bh, bd);
                if (use_bl) ldsm_x4(bl, bd + 10240u);
                #pragma unroll
                for (int half = 0; half < 2; half++) {
                    int nt = ntp * 2 + half;
                    unsigned int h0 = bh[half * 2], h1 = bh[half * 2 + 1];
                    #pragma unroll
                    for (int mt = 0; mt < 2; mt++) {
                        mma16816(acc[mt][nt], a[0][mt], h0, h1);          // Ah*Bh
                        if (use_bl)
                            mma16816(acc[mt][nt], a[0][mt], bl[half * 2], bl[half * 2 + 1]); // Ah*Bl
                        mma16816(acc[mt][nt], a[1][mt], h0, h1);          // Al*Bh
                    }
                }
            }
        }
    }

    #pragma unroll
    for (int mt = 0; mt < 2; mt++)
        #pragma unroll
        for (int nt = 0; nt < 8; nt++) {
            int o = o0 + mt * 16 + g;
            int p = p0 + pb + nt * 8 + 2 * tq;
            float* base = out + ((size_t)(n * 128 + o)) * Psp + p;
            *(float2*)base = make_float2(acc[mt][nt][0], acc[mt][nt][1]);
            *(float2*)(base + (size_t)8 * Psp) = make_float2(acc[mt][nt][2], acc[mt][nt][3]);
        }
}

// ---------------- per-channel batch stats (up to 3 tensors) ----------------
__global__ void stats1x3_kernel(const float* __restrict__ s0,
                                const float* __restrict__ s1,
                                const float* __restrict__ s2) {
    int which = blockIdx.y;
    const float* src = (which == 0) ? s0 : (which == 1) ? s1 : s2;
    int bid = blockIdx.x;            // 2048
    int c = bid >> 4;
    int chunk = bid & 15;
    int nn = chunk >> 1;
    int poff = (chunk & 1) * 4096;
    const float* p = src + ((size_t)(nn * 128 + c)) * Psp + poff;
    int tid = threadIdx.x;
    double s = 0.0, ss = 0.0;
    for (int i = tid; i < 4096; i += 256) {
        float v = p[i];
        s += v;
        ss += (double)v * (double)v;
    }
    __shared__ double sh[256], sh2[256];
    sh[tid] = s; sh2[tid] = ss;
    __syncthreads();
    for (int st = 128; st > 0; st >>= 1) {
        if (tid < st) { sh[tid] += sh[tid + st]; sh2[tid] += sh2[tid + st]; }
        __syncthreads();
    }
    if (tid == 0) {
        g_part[(which * 2048 + bid) * 2] = sh[0];
        g_part[(which * 2048 + bid) * 2 + 1] = sh2[0];
    }
}
// grid blocks: w<2 -> g_part slot w (+slotbase); w==2 -> x from g_pxs
__global__ void stats2_kernel(int slotbase) {
    int c = threadIdx.x;   // 128
    int w = blockIdx.x;
    double s = 0.0, ss = 0.0;
    if (slotbase == 0 && w == 2) {
        int cg = c >> 6, cl = c & 63;
        for (int n = 0; n < 8; n++)
            for (int pg = 0; pg < 128; pg++) {
                int cta = n * 256 + cg * 128 + pg;
                s  += g_pxs[(size_t)cta * 64 + cl];
                ss += g_pxss[(size_t)cta * 64 + cl];
            }
    } else {
        for (int k = 0; k < 16; k++) {
            s  += g_part[((w * 2048) + c * 16 + k) * 2];
            ss += g_part[((w * 2048) + c * 16 + k) * 2 + 1];
        }
    }
    double mean = s / (double)(Nimg * Psp);
    double var  = ss / (double)(Nimg * Psp) - mean * mean;
    g_mean[(slotbase + w) * 128 + c] = (float)mean;
    g_rstd[(slotbase + w) * 128 + c] = (float)(1.0 / sqrt(var + EPS_BN));
    if (slotbase == 0 && w == 0) {
        for (int i = c; i < 2 * Bn * NW * 128; i += 128) g_regsum[i] = 0.f;
    }
}

// ---------------- routing: a_r + top-4 (from fused region sums) ----------------
__global__ void route_kernel() {
    int tid = threadIdx.x;
    if (tid >= Bn * NW) return;
    int b = tid >> 3, w = tid & 7;
    const float* qr = g_regsum + (b * NW + w) * 128;
    float a[NW];
    const float inv = 1.0f / (float)(Tn * Swin);
    for (int v = 0; v < NW; v++) {
        const float* kr = g_regsum + Bn * NW * 128 + (b * NW + v) * 128;
        float s = 0.f;
        for (int c = 0; c < 128; c++) s += (qr[c] * inv) * (kr[c] * inv);
        a[v] = s * 0.25f;
    }
    bool used[NW] = {false};
    for (int r = 0; r < TOPK; r++) {
        float best = -1e30f;
        int bi = -1;
        for (int v = 0; v < NW; v++)
            if (!used[v] && a[v] > best) { best = a[v]; bi = v; }
        used[bi] = true;
        g_topidx[(b * NW + w) * TOPK + r] = bi;
    }
}

// ---------------- fused 3x BN + LIF -> u8 windowed spikes (+ region sums) ----------------
__global__ void bnlif3_kernel(const float* __restrict__ s0, const float* __restrict__ s1,
                              const float* __restrict__ s2,
                              const float* __restrict__ gm0, const float* __restrict__ gm1,
                              const float* __restrict__ gm2,
                              const float* __restrict__ bt0, const float* __restrict__ bt1,
                              const float* __restrict__ bt2,
                              unsigned char* __restrict__ d0,
                              unsigned char* __restrict__ d1,
                              unsigned char* __restrict__ d2) {
    int which = blockIdx.y;
    const float* src  = (which == 0) ? s0 : (which == 1) ? s1 : s2;
    const float* gam  = (which == 0) ? gm0 : (which == 1) ? gm1 : gm2;
    const float* bet  = (which == 0) ? bt0 : (which == 1) ? bt1 : bt2;
    unsigned char* dst = (which == 0) ? d0 : (which == 1) ? d1 : d2;
    int slot = which;
    int e = blockIdx.x * 256 + threadIdx.x;
    int p = e & 8191;
    int c = (e >> 13) & 127;
    int b = e >> 20;
    float m = g_mean[slot * 128 + c], r = g_rstd[slot * 128 + c];
    float gsc = gam[c] * r;
    float bof = bet[c] - m * gsc;
    int d = p >> 10, hg = (p >> 5) & 31, wg = p & 31;
    int wi = (d >> 2) * 4 + (hg >> 4) * 2 + (wg >> 4);
    int s  = (d & 3) * 256 + (hg & 15) * 16 + (wg & 15);
    float v = 0.f;
    float rsum = 0.f;
    #pragma unroll
    for (int t = 0; t < Tn; t++) {
        float raw = src[(size_t)((t * Bn + b) * 128 + c) * Psp + p];
        float xv = raw * gsc + bof;
        rsum += xv;
        v = 0.5f * (v + xv);
        float spk = (v >= 1.0f) ? 1.f : 0.f;
        dst[(size_t)(((t * Bn + b) * NW + wi) * 128 + c) * Swin + s] = (unsigned char)spk;
        v *= (1.f - spk);
    }
    if (which < 2) {
        #pragma unroll
        for (int off = 8; off > 0; off >>= 1)
            rsum += __shfl_down_sync(0xffffffffu, rsum, off);
        if ((threadIdx.x & 15) == 0)
            atomicAdd(&g_regsum[which * (Bn * NW * 128) + (b * NW + wi) * 128 + c], rsum);
    }
}

// ---------------- attention (SIMD-byte, 4 s per thread) ----------------
// grid (2 sc, 8 h, 16 bw), block 128; thread handles 4 consecutive s
__global__ void attn_kernel() {
    int sc = blockIdx.x;
    int h  = blockIdx.y;
    int bw = blockIdx.z;
    int b = bw >> 3, w = bw & 7;
    int s0 = (sc * 128 + threadIdx.x) * 4;

    int j0 = g_topidx[bw * TOPK + 0];
    int j1 = g_topidx[bw * TOPK + 1];
    int j2 = g_topidx[bw * TOPK + 2];
    int j3 = g_topidx[bw * TOPK + 3];

    int d  = (w >> 2) * 4 + (s0 >> 8);
    int hg = ((w >> 1) & 1) * 16 + ((s0 >> 4) & 15);
    int wg = (w & 1) * 16 + (s0 & 15);
    int p  = d * 1024 + hg * 32 + wg;     // p..p+3 for the 4 lanes

    float v[4] = {0.f, 0.f, 0.f, 0.f};
    float v2[16][4];
    #pragma unroll
    for (int dc = 0; dc < 16; dc++)
        #pragma unroll
        for (int ls = 0; ls < 4; ls++) v2[dc][ls] = 0.f;

    #pragma unroll
    for (int t = 0; t < Tn; t++) {
        size_t tb = (size_t)(t * Bn + b);
        size_t qoff  = ((tb * NW + w)  * 128 + h * HDIM) * Swin + s0;
        size_t k0off = ((tb * NW + j0) * 128 + h * HDIM) * Swin + s0;
        size_t k1off = ((tb * NW + j1) * 128 + h * HDIM) * Swin + s0;
        size_t k2off = ((tb * NW + j2) * 128 + h * HDIM) * Swin + s0;
        size_t k3off = ((tb * NW + j3) * 128 + h * HDIM) * Swin + s0;

        unsigned int dotacc = 0;
        unsigned int vs[16];
        #pragma unroll
        for (int dc = 0; dc < 16; dc++) {
            unsigned int q  = *(const unsigned int*)(g_qspk + qoff  + dc * Swin);
            unsigned int k0 = *(const unsigned int*)(g_kspk + k0off + dc * Swin);
            unsigned int k1 = *(const unsigned int*)(g_kspk + k1off + dc * Swin);
            unsigned int k2 = *(const unsigned int*)(g_kspk + k2off + dc * Swin);
            unsigned int k3 = *(const unsigned int*)(g_kspk + k3off + dc * Swin);
            unsigned int kv = __vadd4(__vadd4(k0, k1), __vadd4(k2, k3));
            dotacc = __vadd4(dotacc, kv & __vcmpgtu4(q, 0u));
            unsigned int w0 = *(const unsigned int*)(g_vspk + k0off + dc * Swin);
            unsigned int w1 = *(const unsigned int*)(g_vspk + k1off + dc * Swin);
            unsigned int w2 = *(const unsigned int*)(g_vspk + k2off + dc * Swin);
            unsigned int w3 = *(const unsigned int*)(g_vspk + k3off + dc * Swin);
            vs[dc] = __vadd4(__vadd4(w0, w1), __vadd4(w2, w3));
        }

        float spk[4];
        #pragma unroll
        for (int ls = 0; ls < 4; ls++) {
            float dot = (float)((dotacc >> (8 * ls)) & 0xFFu) * 0.25f;
            v[ls] = 0.5f * (v[ls] + dot);
            spk[ls] = (v[ls] >= 1.0f) ? 1.f : 0.f;
            v[ls] *= (1.f - spk[ls]);
        }

        #pragma unroll
        for (int ls = 0; ls < 4; ls++) {
            unsigned int packs[8];
            #pragma unroll
            for (int dp = 0; dp < 8; dp++) {
                unsigned int pk = 0;
                #pragma unroll
                for (int half = 0; half < 2; half++) {
                    int dc = dp * 2 + half;
                    float vagg = 0.25f * (float)((vs[dc] >> (8 * ls)) & 0xFFu);
                    float ov = spk[ls] * vagg;
                    v2[dc][ls] = 0.5f * (v2[dc][ls] + ov);
                    float s2 = (v2[dc][ls] >= 1.0f) ? 1.f : 0.f;
                    v2[dc][ls] *= (1.f - s2);
                    if (s2 > 0.5f) pk |= (0x3C00u << (16 * half));
                }
                packs[dp] = pk;
            }
            size_t obase = (tb * Psp + p + ls) * 64 + (size_t)h * 8;
            *(uint4*)(g_s2h + obase)     = make_uint4(packs[0], packs[1], packs[2], packs[3]);
            *(uint4*)(g_s2h + obase + 4) = make_uint4(packs[4], packs[5], packs[6], packs[7]);
        }
    }
}

// ---------------- final BN apply ----------------
__global__ void finalize_kernel(const float* __restrict__ gamma,
                                const float* __restrict__ beta,
                                float* __restrict__ out) {
    int e = blockIdx.x * 256 + threadIdx.x;
    if (e >= TOT) return;
    int c = (e >> 13) & 127;
    float m = g_mean[3 * 128 + c], r = g_rstd[3 * 128 + c];
    out[e] = (g_y[e] - m) * r * gamma[c] + beta[c];
}

// ---------------- launch ----------------
extern "C" void kernel_launch(void* const* d_in, const int* in_sizes, int n_in,
                              void* d_out, int out_size) {
    const float* x       = (const float*)d_in[0];
    const float* qw      = (const float*)d_in[1];
    const float* q_gamma = (const float*)d_in[2];
    const float* q_beta  = (const float*)d_in[3];
    const float* kw      = (const float*)d_in[4];
    const float* k_gamma = (const float*)d_in[5];
    const float* k_beta  = (const float*)d_in[6];
    const float* v_gamma = (const float*)d_in[7];
    const float* v_beta  = (const float*)d_in[8];
    const float* pw      = (const float*)d_in[9];
    const float* p_gamma = (const float*)d_in[10];
    const float* p_beta  = (const float*)d_in[11];
    float* out = (float*)d_out;

    float *qpre, *kpre, *y;
    unsigned char *qspk, *kspk, *vspk;
    unsigned int *xh, *xl, *s2h;
    uint4 *wA4, *kwimg, *pwimg;
    cudaGetSymbolAddress((void**)&qpre, g_qpre);
    cudaGetSymbolAddress((void**)&kpre, g_kpre);
    cudaGetSymbolAddress((void**)&qspk, g_qspk);
    cudaGetSymbolAddress((void**)&kspk, g_kspk);
    cudaGetSymbolAddress((void**)&vspk, g_vspk);
    cudaGetSymbolAddress((void**)&y, g_y);
    cudaGetSymbolAddress((void**)&xh, g_xh32);
    cudaGetSymbolAddress((void**)&xl, g_xl32);
    cudaGetSymbolAddress((void**)&s2h, g_s2h);
    cudaGetSymbolAddress((void**)&wA4, g_wA4);
    cudaGetSymbolAddress((void**)&kwimg, g_kwimg);
    cudaGetSymbolAddress((void**)&pwimg, g_pwimg);

    cudaFuncSetAttribute(mma_gemm_kernel,
                         cudaFuncAttributeMaxDynamicSharedMemorySize, SMEM_TOTAL);

    prep_all_kernel<<<2176, 256>>>(x, qw, kw, pw);
    // conv (group 0, 112 stages -> qpre) + kw gemm (group 1, 4 stages -> kpre)
    mma_gemm_kernel<<<1024, 256, SMEM_TOTAL>>>(wA4, 0, 112, qpre,
                                               kwimg, 27, 4, kpre,
                                               1, xh, xl);
    stats1x3_kernel<<<dim3(2048, 2), 256>>>(qpre, kpre, kpre);
    stats2_kernel<<<3, 128>>>(0);     // slots 0,1 from g_part; slot 2 (x) from g_pxs
    bnlif3_kernel<<<dim3((Bn * Cch * Psp) / 256, 3), 256>>>(
        qpre, kpre, x, q_gamma, k_gamma, v_gamma, q_beta, k_beta, v_beta,
        qspk, kspk, vspk);
    route_kernel<<<1, 32>>>();
    attn_kernel<<<dim3(2, 8, 16), 128>>>();
    // pw gemm (group 0 only, 4 stages -> y), spike input: no B low split
    mma_gemm_kernel<<<512, 256, SMEM_TOTAL>>>(pwimg, 27, 4, y,
                                              (const uint4*)0, 0, 0, (float*)0,
                                              0, s2h, s2h);
    stats1x3_kernel<<<dim3(2048, 1), 256>>>(y, y, y);
    stats2_kernel<<<1, 128>>>(3);
    finalize_kernel<<<TOT / 256, 256>>>(p_gamma, p_beta, out);
}

// round 16
// speedup vs baseline: 1.7911x; 1.7911x over previous
#include <cuda_runtime.h>
#include <cuda_fp16.h>
#include <math.h>

// ---------------- problem constants ----------------
#define Tn 4
#define Bn 2
#define Cch 128
#define Psp 8192              // 8*32*32
#define Nimg 8                // Tn*Bn
#define TOT 8388608           // Nimg*Cch*Psp
#define NW 8
#define Swin 1024
#define HDIM 16
#define TOPK 4
#define THETA 0.7f
#define EPS_BN 1e-5
// A: fragment-native layout, 16384 B/stage (no padding)
// B: [2 split][256 p][40 halves] rows of 80 B, 20480 B/stage
#define B_OFF 16384
#define STAGE_BYTES 36864
#define SMEM_TOTAL 110592     // 3 stages

// ---------------- device scratch ----------------
__device__ float g_qpre[TOT];
__device__ float g_kpre[TOT];
__device__ unsigned char g_qspk[TOT];   // u8 spikes, windowed [t][b][w][c][s]
__device__ unsigned char g_kspk[TOT];
__device__ unsigned char g_vspk[TOT];
__device__ float g_y[TOT];
__device__ float g_mean[4 * 128];
__device__ float g_rstd[4 * 128];
__device__ float g_regsum[2 * Bn * NW * 128];   // BN'd window sums (q,k)
__device__ int   g_topidx[Bn * NW * TOPK];
__device__ double g_part[4 * 2048 * 2];

// weight images, fragment-native: per stage 1024 uint4 (16384 B)
__device__ uint4 g_wA4[112 * 1024];
__device__ uint4 g_kwimg[4 * 1024];
__device__ uint4 g_pwimg[4 * 1024];
// x transposed + fp16-split: [n*8192 + p][64 u32]
__device__ unsigned int g_xh32[Nimg * Psp * 64];
__device__ unsigned int g_xl32[Nimg * Psp * 64];
// spike output of attn in fp16 [n][p][c]
__device__ unsigned int g_s2h[TOT / 2];

// ---------------- helpers ----------------
__device__ __forceinline__ unsigned int smem_u32(const void* p) {
    unsigned int a;
    asm("{ .reg .u64 t; cvta.to.shared.u64 t, %1; cvt.u32.u64 %0, t; }" : "=r"(a) : "l"(p));
    return a;
}
__device__ __forceinline__ void cpa16(unsigned int dst, const void* src, int srcbytes) {
    asm volatile("cp.async.cg.shared.global [%0], [%1], 16, %2;"
                 :: "r"(dst), "l"(src), "r"(srcbytes) : "memory");
}
#define CPA_COMMIT() asm volatile("cp.async.commit_group;" ::: "memory")
#define CPA_WAIT1()  asm volatile("cp.async.wait_group 1;" ::: "memory")
#define CPA_WAIT0()  asm volatile("cp.async.wait_group 0;" ::: "memory")

__device__ __forceinline__ void ldsm_x4(unsigned int* r, unsigned int addr) {
    asm volatile("ldmatrix.sync.aligned.m8n8.x4.shared.b16 {%0,%1,%2,%3}, [%4];"
                 : "=r"(r[0]), "=r"(r[1]), "=r"(r[2]), "=r"(r[3]) : "r"(addr));
}
__device__ __forceinline__ void mma16816(float* c, const unsigned int* a,
                                         unsigned int b0, unsigned int b1) {
    asm volatile("mma.sync.aligned.m16n8k16.row.col.f32.f16.f16.f32 "
                 "{%0,%1,%2,%3}, {%4,%5,%6,%7}, {%8,%9}, {%0,%1,%2,%3};"
                 : "+f"(c[0]), "+f"(c[1]), "+f"(c[2]), "+f"(c[3])
                 : "r"(a[0]), "r"(a[1]), "r"(a[2]), "r"(a[3]), "r"(b0), "r"(b1));
}
__device__ __forceinline__ void split2h(float x, unsigned short& h, unsigned short& l) {
    __half hh = __float2half_rn(x);
    float fh = __half2float(hh);
    __half hl = __float2half_rn(x - fh);
    h = __half_as_ushort(hh);
    l = __half_as_ushort(hl);
}

// A image half-index within a stage block (8192 halves):
// [split(2)][koct(4)][ogrp(16)][orow(8)][khalf(8)]
__device__ __forceinline__ int a_img_idx(int split, int o, int kh) {
    return split * 4096 + (kh >> 3) * 1024 + (o >> 3) * 64 + (o & 7) * 8 + (kh & 7);
}

// ---------------- combined prep: xsplit (2048 CTAs) + conv wimg (64) + 1x1 wimg (64) ----
__global__ __launch_bounds__(256) void prep_all_kernel(const float* __restrict__ x,
                                                       const float* __restrict__ qw,
                                                       const float* __restrict__ kw,
                                                       const float* __restrict__ pw) {
    __shared__ float sm[64 * 65];
    int bx = blockIdx.x;
    int tid = threadIdx.x;

    if (bx < 2048) {
        int n  = bx >> 8;
        int cg = (bx >> 7) & 1;
        int pg = bx & 127;
        int c0 = cg * 64, p0 = pg * 64;
        #pragma unroll
        for (int i = 0; i < 16; i++) {
            int idx = tid + i * 256;
            int cc = idx >> 6, pp = idx & 63;
            sm[cc * 65 + pp] = x[((size_t)(n * 128 + c0 + cc)) * Psp + p0 + pp];
        }
        __syncthreads();
        #pragma unroll
        for (int i = 0; i < 8; i++) {
            int idx = tid + i * 256;
            int pp = idx >> 5, k = idx & 31;
            float v0 = sm[(2 * k) * 65 + pp];
            float v1 = sm[(2 * k + 1) * 65 + pp];
            unsigned short h0, l0, h1, l1;
            split2h(v0, h0, l0);
            split2h(v1, h1, l1);
            size_t dst = ((size_t)(n * Psp + p0 + pp)) * 64 + cg * 32 + k;
            g_xh32[dst] = (unsigned int)h0 | ((unsigned int)h1 << 16);
            g_xl32[dst] = (unsigned int)l0 | ((unsigned int)l1 << 16);
        }
        return;
    }
    if (bx < 2112) {
        int t2 = (bx - 2048) * 256 + tid;      // 16384
        int o = t2 >> 7;
        int ic = t2 & 127;
        int kc = ic >> 5;
        int kh = ic & 31;
        unsigned short* img = (unsigned short*)g_wA4;
        float kd = 0.f;
        #pragma unroll
        for (int t = 0; t < 27; t++) {
            float w = qw[o * 3456 + ic * 27 + t];
            if ((t / 9) != 1) kd += w;
            unsigned short h, l;
            split2h(w, h, l);
            int s = t * 4 + kc;
            img[s * 8192 + a_img_idx(0, o, kh)] = h;
            img[s * 8192 + a_img_idx(1, o, kh)] = l;
        }
        {
            unsigned short h, l;
            split2h(-THETA * kd, h, l);
            int s = 27 * 4 + kc;
            img[s * 8192 + a_img_idx(0, o, kh)] = h;
            img[s * 8192 + a_img_idx(1, o, kh)] = l;
        }
        return;
    }
    {
        int t2 = (bx - 2112) * 256 + tid;      // 16384
        int o = t2 >> 7;
        int ic = t2 & 127;
        int s = ic >> 5;
        int kh = ic & 31;
        unsigned short* ki = (unsigned short*)g_kwimg;
        unsigned short* pi = (unsigned short*)g_pwimg;
        unsigned short h, l;
        split2h(kw[o * 128 + ic], h, l);
        ki[s * 8192 + a_img_idx(0, o, kh)] = h;
        ki[s * 8192 + a_img_idx(1, o, kh)] = l;
        split2h(pw[o * 128 + ic], h, l);
        pi[s * 8192 + a_img_idx(0, o, kh)] = h;
        pi[s * 8192 + a_img_idx(1, o, kh)] = l;
    }
}

// ---------------- tensor-core GEMM/conv (fp16 2-split), 3-deep pipeline ----------------
__global__ __launch_bounds__(256, 2) void mma_gemm_kernel(
    const uint4* __restrict__ wimgA, int tapbaseA, int nsA, float* __restrict__ outA,
    const uint4* __restrict__ wimgB, int tapbaseB, int nsB, float* __restrict__ outB,
    int use_bl,
    const unsigned int* __restrict__ xh, const unsigned int* __restrict__ xl)
{
    extern __shared__ __align__(16) unsigned char smem[];
    const unsigned int sbase = smem_u32(smem);
    const int tid = threadIdx.x;
    const int lane = tid & 31, wid = tid >> 5;
    const int g = lane >> 2, tq = lane & 3;

    const int grp = blockIdx.x >> 9;
    const int bid = blockIdx.x & 511;
    const uint4* wimg = grp ? wimgB : wimgA;
    const int tapbase = grp ? tapbaseB : tapbaseA;
    const int nstage  = grp ? nsB : nsA;
    float* out        = grp ? outB : outA;

    const int n  = bid >> 6;
    const int p0 = (bid & 63) << 7;
    const int o0 = (wid >> 1) * 32;
    const int pb = (wid & 1) * 64;

    const int sp = tid & 1, prow = tid >> 1;
    const int pg = p0 + prow;
    const int pd = pg >> 10, ph = (pg >> 5) & 31, pw_ = pg & 31;
    const unsigned int* xsrc = sp ? xl : xh;

    const int l7 = lane & 7, lm = lane >> 3;
    const unsigned int aCom = (unsigned)(((o0 >> 3) + (lm & 1)) * 128
                                         + (lm >> 1) * 2048 + l7 * 16);
    const unsigned int bCom = (unsigned)B_OFF + (unsigned)((pb + ((lm >> 1) << 3) + l7) * 80
                                         + ((lm & 1) << 4));

    float acc[2][8][4];
    #pragma unroll
    for (int mt = 0; mt < 2; mt++)
        #pragma unroll
        for (int nt = 0; nt < 8; nt++)
            #pragma unroll
            for (int q = 0; q < 4; q++) acc[mt][nt][q] = 0.f;

    auto stage_load = [&](int s) {
        unsigned int buf = sbase + (unsigned)(s % 3) * (unsigned)STAGE_BYTES;
        int tap = tapbase + (s >> 2);
        int dd, dh, dw;
        if (tap < 27) { dd = tap / 9 - 1; dh = (tap / 3) % 3 - 1; dw = tap % 3 - 1; }
        else          { dd = 0; dh = 0; dw = 0; }
        const uint4* asrc = wimg + (size_t)s * 1024;
        #pragma unroll
        for (int q = 0; q < 4; q++)
            cpa16(buf + (unsigned)(tid + q * 256) * 16u, asrc + tid + q * 256, 16);
        if (use_bl || sp == 0) {
            int d2 = pd + dd, h2 = ph + dh, w2 = pw_ + dw;
            bool val = ((unsigned)d2 < 8) & ((unsigned)h2 < 32) & ((unsigned)w2 < 32);
            int psrc = val ? (d2 * 1024 + h2 * 32 + w2) : 0;
            int kc = s & 3;
            const uint4* bsrc = (const uint4*)(xsrc + ((size_t)(n * Psp + psrc)) * 64 + kc * 16);
            unsigned int bdst = buf + (unsigned)B_OFF + (unsigned)(sp * 128 + prow) * 80u;
            int sb = val ? 16 : 0;
            #pragma unroll
            for (int q = 0; q < 4; q++)
                cpa16(bdst + q * 16u, bsrc + q, sb);
        }
        CPA_COMMIT();
    };

    stage_load(0);
    if (nstage > 1) stage_load(1);
    for (int s = 0; s < nstage; s++) {
        if (s + 1 < nstage) { CPA_WAIT1(); }
        else                { CPA_WAIT0(); }
        __syncthreads();
        if (s + 2 < nstage) stage_load(s + 2);
        unsigned int buf = sbase + (unsigned)(s % 3) * (unsigned)STAGE_BYTES;
        #pragma unroll
        for (int ks = 0; ks < 2; ks++) {
            unsigned int a[2][2][4];
            #pragma unroll
            for (int sp2 = 0; sp2 < 2; sp2++)
                #pragma unroll
                for (int mt = 0; mt < 2; mt++)
                    ldsm_x4(a[sp2][mt], buf + aCom + (unsigned)sp2 * 8192u
                                        + (unsigned)ks * 4096u + (unsigned)mt * 256u);
            #pragma unroll
            for (int ntp = 0; ntp < 4; ntp++) {
                unsigned int bd = buf + bCom + (unsigned)ntp * 1280u + (unsigned)ks * 32u;
                unsigned int bh[4], bl[4];
                ldsm_x4(bh, bd);
                if (use_bl) ldsm_x4(bl, bd + 10240u);
                #pragma unroll
                for (int half = 0; half < 2; half++) {
                    int nt = ntp * 2 + half;
                    unsigned int h0 = bh[half * 2], h1 = bh[half * 2 + 1];
                    #pragma unroll
                    for (int mt = 0; mt < 2; mt++) {
                        mma16816(acc[mt][nt], a[0][mt], h0, h1);          // Ah*Bh
                        if (use_bl)
                            mma16816(acc[mt][nt], a[0][mt], bl[half * 2], bl[half * 2 + 1]); // Ah*Bl
                        mma16816(acc[mt][nt], a[1][mt], h0, h1);          // Al*Bh
                    }
                }
            }
        }
    }

    #pragma unroll
    for (int mt = 0; mt < 2; mt++)
        #pragma unroll
        for (int nt = 0; nt < 8; nt++) {
            int o = o0 + mt * 16 + g;
            int p = p0 + pb + nt * 8 + 2 * tq;
            float* base = out + ((size_t)(n * 128 + o)) * Psp + p;
            *(float2*)base = make_float2(acc[mt][nt][0], acc[mt][nt][1]);
            *(float2*)(base + (size_t)8 * Psp) = make_float2(acc[mt][nt][2], acc[mt][nt][3]);
        }
}

// ---------------- per-channel batch stats (3 tensors fused) ----------------
__global__ void stats1x3_kernel(const float* __restrict__ s0,
                                const float* __restrict__ s1,
                                const float* __restrict__ s2) {
    int which = blockIdx.y;
    const float* src = (which == 0) ? s0 : (which == 1) ? s1 : s2;
    int bid = blockIdx.x;            // 2048
    int c = bid >> 4;
    int chunk = bid & 15;
    int nn = chunk >> 1;
    int poff = (chunk & 1) * 4096;
    const float* p = src + ((size_t)(nn * 128 + c)) * Psp + poff;
    int tid = threadIdx.x;
    double s = 0.0, ss = 0.0;
    for (int i = tid; i < 4096; i += 256) {
        float v = p[i];
        s += v;
        ss += (double)v * (double)v;
    }
    __shared__ double sh[256], sh2[256];
    sh[tid] = s; sh2[tid] = ss;
    __syncthreads();
    for (int st = 128; st > 0; st >>= 1) {
        if (tid < st) { sh[tid] += sh[tid + st]; sh2[tid] += sh2[tid + st]; }
        __syncthreads();
    }
    if (tid == 0) {
        g_part[(which * 2048 + bid) * 2] = sh[0];
        g_part[(which * 2048 + bid) * 2 + 1] = sh2[0];
    }
}
// grid = nslot blocks; block w handles slot slotbase+w
__global__ void stats2_kernel(int slotbase) {
    int c = threadIdx.x;   // 128
    int w = blockIdx.x;
    double s = 0.0, ss = 0.0;
    for (int k = 0; k < 16; k++) {
        s  += g_part[((w * 2048) + c * 16 + k) * 2];
        ss += g_part[((w * 2048) + c * 16 + k) * 2 + 1];
    }
    double mean = s / (double)(Nimg * Psp);
    double var  = ss / (double)(Nimg * Psp) - mean * mean;
    g_mean[(slotbase + w) * 128 + c] = (float)mean;
    g_rstd[(slotbase + w) * 128 + c] = (float)(1.0 / sqrt(var + EPS_BN));
    if (slotbase == 0 && w == 0) {
        for (int i = c; i < 2 * Bn * NW * 128; i += 128) g_regsum[i] = 0.f;
    }
}

// ---------------- routing: a_r + top-4 (from fused region sums) ----------------
__global__ void route_kernel() {
    int tid = threadIdx.x;
    if (tid >= Bn * NW) return;
    int b = tid >> 3, w = tid & 7;
    const float* qr = g_regsum + (b * NW + w) * 128;
    float a[NW];
    const float inv = 1.0f / (float)(Tn * Swin);
    for (int v = 0; v < NW; v++) {
        const float* kr = g_regsum + Bn * NW * 128 + (b * NW + v) * 128;
        float s = 0.f;
        for (int c = 0; c < 128; c++) s += (qr[c] * inv) * (kr[c] * inv);
        a[v] = s * 0.25f;
    }
    bool used[NW] = {false};
    for (int r = 0; r < TOPK; r++) {
        float best = -1e30f;
        int bi = -1;
        for (int v = 0; v < NW; v++)
            if (!used[v] && a[v] > best) { best = a[v]; bi = v; }
        used[bi] = true;
        g_topidx[(b * NW + w) * TOPK + r] = bi;
    }
}

// ---------------- fused 3x BN + LIF -> u8 windowed spikes, 4 px/thread ----------------
__global__ void bnlif3_kernel(const float* __restrict__ s0, const float* __restrict__ s1,
                              const float* __restrict__ s2,
                              const float* __restrict__ gm0, const float* __restrict__ gm1,
                              const float* __restrict__ gm2,
                              const float* __restrict__ bt0, const float* __restrict__ bt1,
                              const float* __restrict__ bt2,
                              unsigned char* __restrict__ d0,
                              unsigned char* __restrict__ d1,
                              unsigned char* __restrict__ d2) {
    int which = blockIdx.y;
    const float* src  = (which == 0) ? s0 : (which == 1) ? s1 : s2;
    const float* gam  = (which == 0) ? gm0 : (which == 1) ? gm1 : gm2;
    const float* bet  = (which == 0) ? bt0 : (which == 1) ? bt1 : bt2;
    unsigned char* dst = (which == 0) ? d0 : (which == 1) ? d1 : d2;
    int slot = which;
    int e4 = blockIdx.x * 256 + threadIdx.x;   // over (Bn*Cch*Psp)/4
    int base = e4 * 4;
    int p = base & 8191;
    int c = (base >> 13) & 127;
    int b = base >> 20;
    float m = g_mean[slot * 128 + c], r = g_rstd[slot * 128 + c];
    float gsc = gam[c] * r;
    float bof = bet[c] - m * gsc;
    int d = p >> 10, hg = (p >> 5) & 31, wg = p & 31;
    int wi = (d >> 2) * 4 + (hg >> 4) * 2 + (wg >> 4);
    int s  = (d & 3) * 256 + (hg & 15) * 16 + (wg & 15);
    float v[4] = {0.f, 0.f, 0.f, 0.f};
    float rsum = 0.f;
    #pragma unroll
    for (int t = 0; t < Tn; t++) {
        float4 raw = *(const float4*)(src + (size_t)((t * Bn + b) * 128 + c) * Psp + p);
        float xv[4] = {raw.x * gsc + bof, raw.y * gsc + bof,
                       raw.z * gsc + bof, raw.w * gsc + bof};
        unsigned char sb[4];
        #pragma unroll
        for (int i = 0; i < 4; i++) {
            rsum += xv[i];
            v[i] = 0.5f * (v[i] + xv[i]);
            float spk = (v[i] >= 1.0f) ? 1.f : 0.f;
            sb[i] = (unsigned char)spk;
            v[i] *= (1.f - spk);
        }
        uchar4 pk = make_uchar4(sb[0], sb[1], sb[2], sb[3]);
        *(uchar4*)(dst + (size_t)(((t * Bn + b) * NW + wi) * 128 + c) * Swin + s) = pk;
    }
    if (which < 2) {
        // 4 consecutive threads share a window (16 consecutive p)
        rsum += __shfl_down_sync(0xffffffffu, rsum, 2);
        rsum += __shfl_down_sync(0xffffffffu, rsum, 1);
        if ((threadIdx.x & 3) == 0)
            atomicAdd(&g_regsum[which * (Bn * NW * 128) + (b * NW + wi) * 128 + c], rsum);
    }
}

// ---------------- attention: dot + LIF + v_agg + second LIF -> fp16 spikes ----------------
__global__ void attn_kernel() {
    int sc = blockIdx.x;
    int h  = blockIdx.y;
    int bw = blockIdx.z;
    int b = bw >> 3, w = bw & 7;
    int s = sc * 128 + threadIdx.x;

    int j0 = g_topidx[bw * TOPK + 0];
    int j1 = g_topidx[bw * TOPK + 1];
    int j2 = g_topidx[bw * TOPK + 2];
    int j3 = g_topidx[bw * TOPK + 3];

    int d  = (w >> 2) * 4 + (s >> 8);
    int hg = ((w >> 1) & 1) * 16 + ((s >> 4) & 15);
    int wg = (w & 1) * 16 + (s & 15);
    int p  = d * 1024 + hg * 32 + wg;

    float v = 0.f;
    float v2[16];
    #pragma unroll
    for (int dc = 0; dc < 16; dc++) v2[dc] = 0.f;

    #pragma unroll
    for (int t = 0; t < Tn; t++) {
        size_t tb = (size_t)(t * Bn + b);
        const unsigned char* qb  = g_qspk + ((tb * NW + w)  * 128 + h * HDIM) * Swin + s;
        const unsigned char* kb0 = g_kspk + ((tb * NW + j0) * 128 + h * HDIM) * Swin + s;
        const unsigned char* kb1 = g_kspk + ((tb * NW + j1) * 128 + h * HDIM) * Swin + s;
        const unsigned char* kb2 = g_kspk + ((tb * NW + j2) * 128 + h * HDIM) * Swin + s;
        const unsigned char* kb3 = g_kspk + ((tb * NW + j3) * 128 + h * HDIM) * Swin + s;
        int doti = 0;
        #pragma unroll
        for (int dc = 0; dc < HDIM; dc++) {
            int kv = (int)kb0[dc * Swin] + kb1[dc * Swin] + kb2[dc * Swin] + kb3[dc * Swin];
            doti += (int)qb[dc * Swin] * kv;
        }
        float dot = (float)doti * 0.25f;
        v = 0.5f * (v + dot);
        float spk = (v >= 1.0f) ? 1.f : 0.f;
        v *= (1.f - spk);

        const unsigned char* vb0 = g_vspk + ((tb * NW + j0) * 128 + h * HDIM) * Swin + s;
        const unsigned char* vb1 = g_vspk + ((tb * NW + j1) * 128 + h * HDIM) * Swin + s;
        const unsigned char* vb2 = g_vspk + ((tb * NW + j2) * 128 + h * HDIM) * Swin + s;
        const unsigned char* vb3 = g_vspk + ((tb * NW + j3) * 128 + h * HDIM) * Swin + s;
        unsigned int packs[8];
        #pragma unroll
        for (int dp = 0; dp < 8; dp++) {
            unsigned int pk = 0;
            #pragma unroll
            for (int half = 0; half < 2; half++) {
                int dc = dp * 2 + half;
                float vagg = 0.25f * (float)((int)vb0[dc * Swin] + vb1[dc * Swin]
                                           + vb2[dc * Swin] + vb3[dc * Swin]);
                float ov = spk * vagg;
                v2[dc] = 0.5f * (v2[dc] + ov);
                float s2 = (v2[dc] >= 1.0f) ? 1.f : 0.f;
                v2[dc] *= (1.f - s2);
                if (s2 > 0.5f) pk |= (0x3C00u << (16 * half));
            }
            packs[dp] = pk;
        }
        size_t obase = (tb * Psp + p) * 64 + (size_t)h * 8;
        *(uint4*)(g_s2h + obase)     = make_uint4(packs[0], packs[1], packs[2], packs[3]);
        *(uint4*)(g_s2h + obase + 4) = make_uint4(packs[4], packs[5], packs[6], packs[7]);
    }
}

// ---------------- final BN apply ----------------
__global__ void finalize_kernel(const float* __restrict__ gamma,
                                const float* __restrict__ beta,
                                float* __restrict__ out) {
    int e = blockIdx.x * 256 + threadIdx.x;
    if (e >= TOT) return;
    int c = (e >> 13) & 127;
    float m = g_mean[3 * 128 + c], r = g_rstd[3 * 128 + c];
    out[e] = (g_y[e] - m) * r * gamma[c] + beta[c];
}

// ---------------- launch ----------------
extern "C" void kernel_launch(void* const* d_in, const int* in_sizes, int n_in,
                              void* d_out, int out_size) {
    const float* x       = (const float*)d_in[0];
    const float* qw      = (const float*)d_in[1];
    const float* q_gamma = (const float*)d_in[2];
    const float* q_beta  = (const float*)d_in[3];
    const float* kw      = (const float*)d_in[4];
    const float* k_gamma = (const float*)d_in[5];
    const float* k_beta  = (const float*)d_in[6];
    const float* v_gamma = (const float*)d_in[7];
    const float* v_beta  = (const float*)d_in[8];
    const float* pw      = (const float*)d_in[9];
    const float* p_gamma = (const float*)d_in[10];
    const float* p_beta  = (const float*)d_in[11];
    float* out = (float*)d_out;

    float *qpre, *kpre, *y;
    unsigned char *qspk, *kspk, *vspk;
    unsigned int *xh, *xl, *s2h;
    uint4 *wA4, *kwimg, *pwimg;
    cudaGetSymbolAddress((void**)&qpre, g_qpre);
    cudaGetSymbolAddress((void**)&kpre, g_kpre);
    cudaGetSymbolAddress((void**)&qspk, g_qspk);
    cudaGetSymbolAddress((void**)&kspk, g_kspk);
    cudaGetSymbolAddress((void**)&vspk, g_vspk);
    cudaGetSymbolAddress((void**)&y, g_y);
    cudaGetSymbolAddress((void**)&xh, g_xh32);
    cudaGetSymbolAddress((void**)&xl, g_xl32);
    cudaGetSymbolAddress((void**)&s2h, g_s2h);
    cudaGetSymbolAddress((void**)&wA4, g_wA4);
    cudaGetSymbolAddress((void**)&kwimg, g_kwimg);
    cudaGetSymbolAddress((void**)&pwimg, g_pwimg);

    cudaFuncSetAttribute(mma_gemm_kernel,
                         cudaFuncAttributeMaxDynamicSharedMemorySize, SMEM_TOTAL);

    prep_all_kernel<<<2176, 256>>>(x, qw, kw, pw);
    // conv (group 0, 112 stages -> qpre) + kw gemm (group 1, 4 stages -> kpre)
    mma_gemm_kernel<<<1024, 256, SMEM_TOTAL>>>(wA4, 0, 112, qpre,
                                               kwimg, 27, 4, kpre,
                                               1, xh, xl);
    stats1x3_kernel<<<dim3(2048, 3), 256>>>(qpre, kpre, x);
    stats2_kernel<<<3, 128>>>(0);                       // slots 0-2 + zero regsum
    bnlif3_kernel<<<dim3((Bn * Cch * Psp) / 1024, 3), 256>>>(
        qpre, kpre, x, q_gamma, k_gamma, v_gamma, q_beta, k_beta, v_beta,
        qspk, kspk, vspk);
    route_kernel<<<1, 32>>>();
    attn_kernel<<<dim3(8, 8, 16), 128>>>();
    // pw gemm (group 0 only, 4 stages -> y), spike input: no B low split
    mma_gemm_kernel<<<512, 256, SMEM_TOTAL>>>(pwimg, 27, 4, y,
                                              (const uint4*)0, 0, 0, (float*)0,
                                              0, s2h, s2h);
    stats1x3_kernel<<<dim3(2048, 1), 256>>>(y, y, y);
    stats2_kernel<<<1, 128>>>(3);
    finalize_kernel<<<TOT / 256, 256>>>(p_gamma, p_beta, out);
}